// round 1
// baseline (speedup 1.0000x reference)
#include <cuda_runtime.h>

#define BB 32
#define TT 4096
#define PP 512
#define WW 128
#define NMEL 80
#define FILT 256
#define PDIM 64
#define KK 9
#define PAD 4
#define TILE 32

// ---------------- device scratch (static globals; no runtime allocation) ------------
__device__ float g_x1[(size_t)BB * TT * FILT];      // conv1+LN output  [B,T,256]
__device__ float g_x2[(size_t)BB * TT * FILT];      // conv2+LN output  [B,T,256]
__device__ float g_ph[(size_t)BB * PP * FILT];      // phone means     [B,P,256]
__device__ float g_wd[(size_t)BB * WW * FILT];      // word means      [B,W,256]
__device__ float g_z [(size_t)BB * WW * PDIM];      // word MLP out    [B,W,64]
__device__ float g_wT1[NMEL * KK * FILT];           // conv1 weights [cin*k][cout]
__device__ float g_wT2[FILT * KK * FILT];           // conv2 weights [cin*k][cout]
__device__ int   g_pcum[BB * PP];                   // inclusive cumsum of durations
__device__ int   g_wcum[BB * WW];                   // inclusive cumsum of word lens

// ---------------- prep: weight transpose + segment scans ---------------------------
__global__ void transpose1_kernel(const float* __restrict__ src) {
    int tid = blockIdx.x * blockDim.x + threadIdx.x;
    const int RK = NMEL * KK;                       // 720
    if (tid < FILT * RK) {
        int c = tid / RK, r = tid - c * RK;         // src[c][r]
        g_wT1[r * FILT + c] = src[tid];
    }
}
__global__ void transpose2_kernel(const float* __restrict__ src) {
    int tid = blockIdx.x * blockDim.x + threadIdx.x;
    const int RK = FILT * KK;                       // 2304
    if (tid < FILT * RK) {
        int c = tid / RK, r = tid - c * RK;
        g_wT2[r * FILT + c] = src[tid];
    }
}
__global__ void scan_kernel(const int* __restrict__ dur, const int* __restrict__ wpl) {
    int b = blockIdx.x;
    if (threadIdx.x == 0) {
        int s = 0;
        for (int p = 0; p < PP; p++) { s += dur[b * PP + p]; g_pcum[b * PP + p] = s; }
        s = 0;
        for (int w = 0; w < WW; w++) { s += wpl[b * WW + w]; g_wcum[b * WW + w] = s; }
    }
}

// ---------------- fused conv1d + bias + relu + layernorm ----------------------------
// Block: 256 threads (one per output channel), 32-frame tile. grid = (T/TILE, B).
template <int CIN>
__global__ void __launch_bounds__(256) conv_relu_ln(
    const float* __restrict__ xin,   // [B,T,CIN] channel-contiguous
    const float* __restrict__ wT,    // [CIN*K][FILT]
    const float* __restrict__ bias,
    const float* __restrict__ gamma,
    const float* __restrict__ beta,
    float* __restrict__ xout)        // [B,T,FILT]
{
    constexpr int ROWS    = TILE + 2 * PAD;         // 40 input rows (halo)
    constexpr int INELEMS = ROWS * CIN;
    constexpr bool REUSE  = (INELEMS >= TILE * FILT);
    constexpr int SMEMSZ  = REUSE ? INELEMS : (INELEMS + TILE * FILT);
    __shared__ float smem[SMEMSZ];
    __shared__ float s_mean[TILE], s_rstd[TILE];
    float* sh_in  = smem;
    float* sh_out = REUSE ? smem : (smem + INELEMS);

    int b  = blockIdx.y;
    int t0 = blockIdx.x * TILE;
    int c  = threadIdx.x;

    // stage input tile (zero-padded halo)
    const float* xb = xin + (size_t)b * TT * CIN;
    for (int idx = c; idx < INELEMS; idx += 256) {
        int f = idx / CIN, ci = idx - f * CIN;
        int t = t0 + f - PAD;
        sh_in[idx] = (t >= 0 && t < TT) ? xb[(size_t)t * CIN + ci] : 0.f;
    }
    __syncthreads();

    float acc[TILE];
#pragma unroll
    for (int f = 0; f < TILE; f++) acc[f] = 0.f;

    for (int ci = 0; ci < CIN; ci++) {
        float xr[ROWS];
#pragma unroll
        for (int r = 0; r < ROWS; r++) xr[r] = sh_in[r * CIN + ci];   // broadcast LDS
        const float* wrow = wT + (ci * KK) * FILT + c;                // coalesced LDG
#pragma unroll
        for (int k = 0; k < KK; k++) {
            float wv = wrow[k * FILT];
#pragma unroll
            for (int f = 0; f < TILE; f++) acc[f] += wv * xr[f + k];
        }
    }
    __syncthreads();   // done reading sh_in (needed for the REUSE overlap)

    // bias + relu -> staging for LN
    float bv = bias[c];
#pragma unroll
    for (int f = 0; f < TILE; f++)
        sh_out[f * FILT + c] = fmaxf(acc[f] + bv, 0.f);
    __syncthreads();

    // per-frame LN stats: 8 warps x 4 frames
    int warp = c >> 5, lane = c & 31;
#pragma unroll
    for (int j = 0; j < TILE / 8; j++) {
        int f = warp * (TILE / 8) + j;
        float s = 0.f, s2 = 0.f;
#pragma unroll
        for (int q = 0; q < FILT / 32; q++) {
            float v = sh_out[f * FILT + lane + q * 32];
            s += v; s2 += v * v;
        }
#pragma unroll
        for (int off = 16; off > 0; off >>= 1) {
            s  += __shfl_xor_sync(0xffffffffu, s,  off);
            s2 += __shfl_xor_sync(0xffffffffu, s2, off);
        }
        if (lane == 0) {
            float m   = s / FILT;
            float var = s2 / FILT - m * m;
            s_mean[f] = m;
            s_rstd[f] = rsqrtf(var + 1e-5f);
        }
    }
    __syncthreads();

    float gv = gamma[c], btv = beta[c];
    float* ob = xout + ((size_t)b * TT + t0) * FILT + c;
#pragma unroll
    for (int f = 0; f < TILE; f++) {
        float v = (sh_out[f * FILT + c] - s_mean[f]) * s_rstd[f] * gv + btv;
        ob[(size_t)f * FILT] = v;
    }
}

// ---------------- phone-level mean pool ---------------------------------------------
__global__ void phone_pool_kernel(const int* __restrict__ dur) {
    int b = blockIdx.y, p = blockIdx.x, c = threadIdx.x;
    int start = p ? g_pcum[b * PP + p - 1] : 0;
    int end   = g_pcum[b * PP + p];
    if (start > TT) start = TT;
    if (end   > TT) end   = TT;
    float s = 0.f;
    for (int t = start; t < end; t++)
        s += g_x2[((size_t)(b * TT + t)) * FILT + c];
    int d = dur[b * PP + p]; if (d < 1) d = 1;
    g_ph[((size_t)(b * PP + p)) * FILT + c] = s / (float)d;
}

// ---------------- word-level mean pool ----------------------------------------------
__global__ void word_pool_kernel(const int* __restrict__ wpl) {
    int b = blockIdx.y, w = blockIdx.x, c = threadIdx.x;
    int start = w ? g_wcum[b * WW + w - 1] : 0;
    int end   = g_wcum[b * WW + w];
    if (start > PP) start = PP;
    if (end   > PP) end   = PP;
    float s = 0.f;
    for (int p = start; p < end; p++)
        s += g_ph[((size_t)(b * PP + p)) * FILT + c];
    int d = wpl[b * WW + w]; if (d < 1) d = 1;
    g_wd[((size_t)(b * WW + w)) * FILT + c] = s / (float)d;
}

// ---------------- 2-layer MLP (relu(x@w1+b1) -> relu(@w2+b2)) -----------------------
// Block handles 32 words of one batch. grid = (W/32, B).
__global__ void __launch_bounds__(256) mlp_kernel(
    const float* __restrict__ w1, const float* __restrict__ b1,
    const float* __restrict__ w2, const float* __restrict__ b2)
{
    __shared__ float sh[32 * FILT];                  // 32 KB
    int b = blockIdx.y, w0 = blockIdx.x * 32, o = threadIdx.x;

    for (int idx = o; idx < 32 * FILT; idx += 256)
        sh[idx] = g_wd[((size_t)(b * WW + w0)) * FILT + idx];
    __syncthreads();

    float acc[32];
    float bv = b1[o];
#pragma unroll
    for (int m = 0; m < 32; m++) acc[m] = bv;
    for (int i = 0; i < FILT; i++) {
        float wv = w1[i * FILT + o];
#pragma unroll
        for (int m = 0; m < 32; m++) acc[m] += sh[m * FILT + i] * wv;
    }
    __syncthreads();
#pragma unroll
    for (int m = 0; m < 32; m++)
        sh[m * FILT + o] = fmaxf(acc[m], 0.f);       // hidden activations
    __syncthreads();

    int oo = o & (PDIM - 1);                         // 0..63
    int mg = o >> 6;                                 // 4 groups of 8 words
    for (int m = mg * 8; m < mg * 8 + 8; m++) {
        float a = b2[oo];
        for (int i = 0; i < FILT; i++)
            a += sh[m * FILT + i] * w2[i * PDIM + oo];
        g_z[((size_t)(b * WW + w0 + m)) * PDIM + oo] = fmaxf(a, 0.f);
    }
}

// ---------------- expand words -> phones + mask -------------------------------------
__global__ void expand_kernel(const unsigned char* __restrict__ mask,
                              float* __restrict__ out)
{
    int b = blockIdx.y, p = blockIdx.x, o = threadIdx.x;
    const int* wc = g_wcum + b * WW;
    // searchsorted(bounds, p, side='right'): first w with bounds[w] > p
    int lo = 0, hi = WW;
    while (lo < hi) {
        int mid = (lo + hi) >> 1;
        if (wc[mid] <= p) lo = mid + 1; else hi = mid;
    }
    int wid = lo; if (wid > WW - 1) wid = WW - 1;
    float v = g_z[((size_t)(b * WW + wid)) * PDIM + o];
    if (mask[b * PP + p]) v = 0.f;
    out[((size_t)(b * PP + p)) * PDIM + o] = v;
}

// ---------------- launch -------------------------------------------------------------
extern "C" void kernel_launch(void* const* d_in, const int* in_sizes, int n_in,
                              void* d_out, int out_size)
{
    const unsigned char* mask = (const unsigned char*)d_in[0];
    const float* mels      = (const float*)d_in[1];
    // d_in[2] = mel_mask (unused by reference)
    const int*   durations = (const int*)d_in[3];
    const int*   wpl       = (const int*)d_in[4];
    const float* c1w = (const float*)d_in[5];
    const float* c1b = (const float*)d_in[6];
    const float* l1g = (const float*)d_in[7];
    const float* l1b = (const float*)d_in[8];
    const float* c2w = (const float*)d_in[9];
    const float* c2b = (const float*)d_in[10];
    const float* l2g = (const float*)d_in[11];
    const float* l2b = (const float*)d_in[12];
    const float* w1  = (const float*)d_in[13];
    const float* b1  = (const float*)d_in[14];
    const float* w2  = (const float*)d_in[15];
    const float* b2  = (const float*)d_in[16];
    float* out = (float*)d_out;

    float *p_wT1, *p_wT2, *p_x1, *p_x2;
    cudaGetSymbolAddress((void**)&p_wT1, g_wT1);
    cudaGetSymbolAddress((void**)&p_wT2, g_wT2);
    cudaGetSymbolAddress((void**)&p_x1,  g_x1);
    cudaGetSymbolAddress((void**)&p_x2,  g_x2);

    transpose1_kernel<<<(FILT * NMEL * KK + 255) / 256, 256>>>(c1w);
    transpose2_kernel<<<(FILT * FILT * KK + 255) / 256, 256>>>(c2w);
    scan_kernel<<<BB, 1>>>(durations, wpl);

    dim3 cgrid(TT / TILE, BB);
    conv_relu_ln<NMEL><<<cgrid, 256>>>(mels, p_wT1, c1b, l1g, l1b, p_x1);
    conv_relu_ln<FILT><<<cgrid, 256>>>(p_x1, p_wT2, c2b, l2g, l2b, p_x2);

    phone_pool_kernel<<<dim3(PP, BB), FILT>>>(durations);
    word_pool_kernel<<<dim3(WW, BB), FILT>>>(wpl);
    mlp_kernel<<<dim3(WW / 32, BB), 256>>>(w1, b1, w2, b2);
    expand_kernel<<<dim3(PP, BB), PDIM>>>(mask, out);
}

// round 3
// speedup vs baseline: 1.8543x; 1.8543x over previous
#include <cuda_runtime.h>
#include <cuda_bf16.h>
#include <cstdint>

#define BB 32
#define TT 4096
#define PP 512
#define WW 128
#define NMEL 80
#define FILT 256
#define PDIM 64
#define KK 9
#define PAD 4

#define BM 128
#define ASTR 40                         // padded smem stride (bf16 elems), conflict-free
#define A_TILE (BM * ASTR)              // 5120 bf16
#define B_TILE (FILT * ASTR)            // 10240 bf16
#define DYNSMEM 131072                  // staging 128x256 fp32 dominates

// ---------------- device scratch ----------------------------------------------------
__device__ float g_x1[(size_t)BB * TT * FILT];
__device__ float g_x2[(size_t)BB * TT * FILT];
__device__ __nv_bfloat16 g_w1h[KK * FILT * NMEL];
__device__ __nv_bfloat16 g_w1m[KK * FILT * NMEL];
__device__ __nv_bfloat16 g_w2h[KK * FILT * FILT];
__device__ __nv_bfloat16 g_w2m[KK * FILT * FILT];
__device__ float g_ph[(size_t)BB * PP * FILT];
__device__ float g_wd[(size_t)BB * WW * FILT];
__device__ float g_z [(size_t)BB * WW * PDIM];
__device__ int   g_pcum[BB * PP];
__device__ int   g_wcum[BB * WW];

// ---------------- helpers ------------------------------------------------------------
__device__ __forceinline__ uint32_t smem_u32(const void* p) {
    return (uint32_t)__cvta_generic_to_shared(p);
}
#define CP16(dst_u32, src_ptr) \
    asm volatile("cp.async.cg.shared.global [%0], [%1], 16;" :: "r"(dst_u32), "l"(src_ptr) : "memory")
#define CP_COMMIT() asm volatile("cp.async.commit_group;" ::: "memory")
#define CP_WAIT0()  asm volatile("cp.async.wait_group 0;" ::: "memory")

#define MMA_BF16(d, a, b) \
    asm volatile("mma.sync.aligned.m16n8k16.row.col.f32.bf16.bf16.f32 " \
        "{%0,%1,%2,%3},{%4,%5,%6,%7},{%8,%9},{%0,%1,%2,%3};" \
        : "+f"((d)[0]), "+f"((d)[1]), "+f"((d)[2]), "+f"((d)[3]) \
        : "r"((a)[0]), "r"((a)[1]), "r"((a)[2]), "r"((a)[3]), "r"((b)[0]), "r"((b)[1]))

__device__ __forceinline__ uint32_t pack_hi(float x0, float x1) {
    __nv_bfloat162 t(__float2bfloat16_rn(x0), __float2bfloat16_rn(x1));
    return *reinterpret_cast<uint32_t*>(&t);
}
__device__ __forceinline__ uint32_t pack_mid(float x0, float x1) {
    float h0 = __bfloat162float(__float2bfloat16_rn(x0));
    float h1 = __bfloat162float(__float2bfloat16_rn(x1));
    __nv_bfloat162 t(__float2bfloat16_rn(x0 - h0), __float2bfloat16_rn(x1 - h1));
    return *reinterpret_cast<uint32_t*>(&t);
}

// ---------------- prep kernels -------------------------------------------------------
template <int CIN>
__global__ void wsplit_kernel(const float* __restrict__ w,
                              __nv_bfloat16* __restrict__ wh,
                              __nv_bfloat16* __restrict__ wm) {
    int i = blockIdx.x * blockDim.x + threadIdx.x;      // [tap][co][ci]
    if (i < KK * FILT * CIN) {
        int ci = i % CIN;
        int co = (i / CIN) % FILT;
        int tap = i / (CIN * FILT);
        float x = w[(co * CIN + ci) * KK + tap];
        __nv_bfloat16 h = __float2bfloat16_rn(x);
        wh[i] = h;
        wm[i] = __float2bfloat16_rn(x - __bfloat162float(h));
    }
}
__global__ void scan_kernel(const int* __restrict__ dur, const int* __restrict__ wpl) {
    int b = blockIdx.x;
    if (threadIdx.x == 0) {
        int s = 0;
        for (int p = 0; p < PP; p++) { s += dur[b * PP + p]; g_pcum[b * PP + p] = s; }
        s = 0;
        for (int w = 0; w < WW; w++) { s += wpl[b * WW + w]; g_wcum[b * WW + w] = s; }
    }
}

// ---------------- fused conv(mma.sync bf16x3) + bias + relu + LN --------------------
// block: 256 thr (8 warps, 2m x 4n), tile BM=128 frames x 256 cout, K = 9 taps x CIN.
template <int CIN>
__global__ void __launch_bounds__(256, 1) conv_mma(
    const float* __restrict__ src,                 // [B,T,CIN] fp32
    const __nv_bfloat16* __restrict__ wbh,         // [tap][co][ci]
    const __nv_bfloat16* __restrict__ wbm,
    const float* __restrict__ bias, const float* __restrict__ gamma,
    const float* __restrict__ beta, float* __restrict__ out)
{
    constexpr int CHUNKS = (CIN + 31) / 32;         // 80->3, 256->8
    constexpr int NST = KK * CHUNKS;

    extern __shared__ char dynsm[];
    __nv_bfloat16* sm_bf = (__nv_bfloat16*)dynsm;
    // A: buf*2*A_TILE (+A_TILE for mid); B: base 4*A_TILE, buf*2*B_TILE (+B_TILE mid)
    float* sStage = (float*)dynsm;

    __shared__ float s_sum[BM], s_sum2[BM];
    __shared__ float sB[FILT], sG[FILT], sE[FILT];

    const int tid = threadIdx.x;
    const int wid = tid >> 5, lane = tid & 31;
    const int wm = wid & 1, wn = wid >> 1;          // 2 x 4 warps
    const int r = lane >> 2, cq = lane & 3;
    const int b = blockIdx.y, t0 = blockIdx.x * BM;

    if (tid < FILT) { sB[tid] = bias[tid]; sG[tid] = gamma[tid]; sE[tid] = beta[tid]; }

    float acc[4][8][4];
#pragma unroll
    for (int mt = 0; mt < 4; mt++)
#pragma unroll
        for (int nt = 0; nt < 8; nt++)
#pragma unroll
            for (int i = 0; i < 4; i++) acc[mt][nt][i] = 0.f;

    const float* srcb = src + (size_t)b * TT * CIN;

    // stage meta
    auto stage_tap = [](int s) { return s / CHUNKS; };
    auto stage_ci0 = [](int s) { return (s % CHUNKS) * 32; };
    auto stage_kc  = [](int s) { int c = s % CHUNKS; int rem = CIN - c * 32; return rem < 32 ? rem : 32; };

    // ---- A global prefetch (regs): thread row = tid>>1, half = tid&1, 16 floats
    const int arow = tid >> 1, ahalf = tid & 1;
    float4 apre[4];
    auto ldgA = [&](int s) {
        int tap = stage_tap(s), ci0 = stage_ci0(s), kc = stage_kc(s);
        int trow = t0 + arow + tap - PAD;
        bool ok = (trow >= 0 && trow < TT) && (ahalf * 16 < kc);
        const float4* p = ok ? (const float4*)(srcb + (size_t)trow * CIN + ci0 + ahalf * 16) : nullptr;
#pragma unroll
        for (int j = 0; j < 4; j++)
            apre[j] = ok ? p[j] : make_float4(0.f, 0.f, 0.f, 0.f);
    };
    auto stsA = [&](int s, int buf) {
        int kc = stage_kc(s);
        if (ahalf * 16 >= kc) return;
        __nv_bfloat16* Ah = sm_bf + buf * 2 * A_TILE;
        __nv_bfloat16* Am = Ah + A_TILE;
        int base = arow * ASTR + ahalf * 16;
#pragma unroll
        for (int j = 0; j < 4; j++) {
            float x0 = apre[j].x, x1 = apre[j].y, x2 = apre[j].z, x3 = apre[j].w;
            *(uint32_t*)(Ah + base + j * 4)     = pack_hi(x0, x1);
            *(uint32_t*)(Ah + base + j * 4 + 2) = pack_hi(x2, x3);
            *(uint32_t*)(Am + base + j * 4)     = pack_mid(x0, x1);
            *(uint32_t*)(Am + base + j * 4 + 2) = pack_mid(x2, x3);
        }
    };
    auto cpB = [&](int s, int buf) {
        int tap = stage_tap(s), ci0 = stage_ci0(s), kc = stage_kc(s);
        int co = tid;                                   // 256 rows
        const __nv_bfloat16* sh = wbh + ((size_t)tap * FILT + co) * CIN + ci0;
        const __nv_bfloat16* sm = wbm + ((size_t)tap * FILT + co) * CIN + ci0;
        uint32_t dh = smem_u32(sm_bf + 4 * A_TILE + buf * 2 * B_TILE + co * ASTR);
        uint32_t dm = dh + B_TILE * 2;
        int nchunks = kc >> 3;                          // 16B chunks
#pragma unroll
        for (int j = 0; j < 4; j++) {
            if (j < nchunks) {
                CP16(dh + j * 16, sh + j * 8);
                CP16(dm + j * 16, sm + j * 8);
            }
        }
    };

    // ---- pipeline
    ldgA(0);
    stsA(0, 0);
    cpB(0, 0);
    CP_COMMIT();

    for (int s = 0; s < NST; s++) {
        int buf = s & 1;
        if (s + 1 < NST) ldgA(s + 1);
        CP_WAIT0();
        __syncthreads();
        if (s + 1 < NST) { cpB(s + 1, buf ^ 1); CP_COMMIT(); stsA(s + 1, buf ^ 1); }

        const __nv_bfloat16* Ah = sm_bf + buf * 2 * A_TILE;
        const __nv_bfloat16* Am = Ah + A_TILE;
        const __nv_bfloat16* Bh = sm_bf + 4 * A_TILE + buf * 2 * B_TILE;
        const __nv_bfloat16* Bm = Bh + B_TILE;
        int nk16 = stage_kc(s) >> 4;                    // 2 or 1

        for (int kk = 0; kk < nk16; kk++) {
            int kb = kk * 16;
            uint32_t ah[4][4], bh[8][2], scr[16];
#pragma unroll
            for (int mt = 0; mt < 4; mt++) {
                int a0 = (wm * 64 + mt * 16 + r) * ASTR + kb + 2 * cq;
                ah[mt][0] = *(const uint32_t*)(Ah + a0);
                ah[mt][1] = *(const uint32_t*)(Ah + a0 + 8 * ASTR);
                ah[mt][2] = *(const uint32_t*)(Ah + a0 + 8);
                ah[mt][3] = *(const uint32_t*)(Ah + a0 + 8 * ASTR + 8);
            }
#pragma unroll
            for (int nt = 0; nt < 8; nt++) {
                int b0 = (wn * 64 + nt * 8 + r) * ASTR + kb + 2 * cq;
                bh[nt][0] = *(const uint32_t*)(Bh + b0);
                bh[nt][1] = *(const uint32_t*)(Bh + b0 + 8);
            }
#pragma unroll
            for (int mt = 0; mt < 4; mt++)
#pragma unroll
                for (int nt = 0; nt < 8; nt++) MMA_BF16(acc[mt][nt], ah[mt], bh[nt]);

            // A_mid x B_hi
#pragma unroll
            for (int mt = 0; mt < 4; mt++) {
                int a0 = (wm * 64 + mt * 16 + r) * ASTR + kb + 2 * cq;
                scr[mt * 4 + 0] = *(const uint32_t*)(Am + a0);
                scr[mt * 4 + 1] = *(const uint32_t*)(Am + a0 + 8 * ASTR);
                scr[mt * 4 + 2] = *(const uint32_t*)(Am + a0 + 8);
                scr[mt * 4 + 3] = *(const uint32_t*)(Am + a0 + 8 * ASTR + 8);
            }
#pragma unroll
            for (int mt = 0; mt < 4; mt++)
#pragma unroll
                for (int nt = 0; nt < 8; nt++) MMA_BF16(acc[mt][nt], &scr[mt * 4], bh[nt]);

            // A_hi x B_mid
#pragma unroll
            for (int nt = 0; nt < 8; nt++) {
                int b0 = (wn * 64 + nt * 8 + r) * ASTR + kb + 2 * cq;
                scr[nt * 2 + 0] = *(const uint32_t*)(Bm + b0);
                scr[nt * 2 + 1] = *(const uint32_t*)(Bm + b0 + 8);
            }
#pragma unroll
            for (int mt = 0; mt < 4; mt++)
#pragma unroll
                for (int nt = 0; nt < 8; nt++) MMA_BF16(acc[mt][nt], ah[mt], &scr[nt * 2]);
        }
    }

    // ---------------- epilogue: bias + relu + LN ----------------
    __syncthreads();
    if (tid < BM) { s_sum[tid] = 0.f; s_sum2[tid] = 0.f; }
    __syncthreads();

#pragma unroll
    for (int mt = 0; mt < 4; mt++) {
        int R0 = wm * 64 + mt * 16 + r;
        float s0 = 0.f, q0 = 0.f, s1 = 0.f, q1 = 0.f;
#pragma unroll
        for (int nt = 0; nt < 8; nt++) {
            int C = wn * 64 + nt * 8 + 2 * cq;
            float b0 = sB[C], b1 = sB[C + 1];
            float v;
            v = fmaxf(acc[mt][nt][0] + b0, 0.f); acc[mt][nt][0] = v; s0 += v; q0 += v * v;
            v = fmaxf(acc[mt][nt][1] + b1, 0.f); acc[mt][nt][1] = v; s0 += v; q0 += v * v;
            v = fmaxf(acc[mt][nt][2] + b0, 0.f); acc[mt][nt][2] = v; s1 += v; q1 += v * v;
            v = fmaxf(acc[mt][nt][3] + b1, 0.f); acc[mt][nt][3] = v; s1 += v; q1 += v * v;
        }
#pragma unroll
        for (int off = 1; off <= 2; off <<= 1) {
            s0 += __shfl_xor_sync(0xffffffffu, s0, off);
            q0 += __shfl_xor_sync(0xffffffffu, q0, off);
            s1 += __shfl_xor_sync(0xffffffffu, s1, off);
            q1 += __shfl_xor_sync(0xffffffffu, q1, off);
        }
        if (cq == 0) {
            atomicAdd(&s_sum[R0], s0);  atomicAdd(&s_sum2[R0], q0);
            atomicAdd(&s_sum[R0 + 8], s1); atomicAdd(&s_sum2[R0 + 8], q1);
        }
    }
    __syncthreads();
    if (tid < BM) {
        float m = s_sum[tid] * (1.f / FILT);
        float v = s_sum2[tid] * (1.f / FILT) - m * m;
        s_sum[tid] = m;
        s_sum2[tid] = rsqrtf(v + 1e-5f);
    }
    __syncthreads();

#pragma unroll
    for (int mt = 0; mt < 4; mt++) {
        int R0 = wm * 64 + mt * 16 + r;
        float m0 = s_sum[R0], rs0 = s_sum2[R0];
        float m1 = s_sum[R0 + 8], rs1 = s_sum2[R0 + 8];
#pragma unroll
        for (int nt = 0; nt < 8; nt++) {
            int C = wn * 64 + nt * 8 + 2 * cq;
            float g0 = sG[C], g1 = sG[C + 1], e0 = sE[C], e1 = sE[C + 1];
            sStage[R0 * FILT + C]           = (acc[mt][nt][0] - m0) * rs0 * g0 + e0;
            sStage[R0 * FILT + C + 1]       = (acc[mt][nt][1] - m0) * rs0 * g1 + e1;
            sStage[(R0 + 8) * FILT + C]     = (acc[mt][nt][2] - m1) * rs1 * g0 + e0;
            sStage[(R0 + 8) * FILT + C + 1] = (acc[mt][nt][3] - m1) * rs1 * g1 + e1;
        }
    }
    __syncthreads();

    float4* op = (float4*)(out + ((size_t)b * TT + t0) * FILT);
    const float4* sp = (const float4*)sStage;
#pragma unroll
    for (int i = 0; i < 32; i++) op[i * 256 + tid] = sp[i * 256 + tid];
}

// ---------------- pooling / mlp / expand (validated round 1) ------------------------
__global__ void phone_pool_kernel(const int* __restrict__ dur) {
    int b = blockIdx.y, p = blockIdx.x, c = threadIdx.x;
    int start = p ? g_pcum[b * PP + p - 1] : 0;
    int end = g_pcum[b * PP + p];
    if (start > TT) start = TT;
    if (end > TT) end = TT;
    float s = 0.f;
    for (int t = start; t < end; t++) s += g_x2[((size_t)(b * TT + t)) * FILT + c];
    int d = dur[b * PP + p]; if (d < 1) d = 1;
    g_ph[((size_t)(b * PP + p)) * FILT + c] = s / (float)d;
}
__global__ void word_pool_kernel(const int* __restrict__ wpl) {
    int b = blockIdx.y, w = blockIdx.x, c = threadIdx.x;
    int start = w ? g_wcum[b * WW + w - 1] : 0;
    int end = g_wcum[b * WW + w];
    if (start > PP) start = PP;
    if (end > PP) end = PP;
    float s = 0.f;
    for (int p = start; p < end; p++) s += g_ph[((size_t)(b * PP + p)) * FILT + c];
    int d = wpl[b * WW + w]; if (d < 1) d = 1;
    g_wd[((size_t)(b * WW + w)) * FILT + c] = s / (float)d;
}
__global__ void __launch_bounds__(256) mlp_kernel(
    const float* __restrict__ w1, const float* __restrict__ b1,
    const float* __restrict__ w2, const float* __restrict__ b2)
{
    __shared__ float sh[32 * FILT];
    int b = blockIdx.y, w0 = blockIdx.x * 32, o = threadIdx.x;
    for (int idx = o; idx < 32 * FILT; idx += 256)
        sh[idx] = g_wd[((size_t)(b * WW + w0)) * FILT + idx];
    __syncthreads();
    float acc[32];
    float bv = b1[o];
#pragma unroll
    for (int m = 0; m < 32; m++) acc[m] = bv;
    for (int i = 0; i < FILT; i++) {
        float wv = w1[i * FILT + o];
#pragma unroll
        for (int m = 0; m < 32; m++) acc[m] += sh[m * FILT + i] * wv;
    }
    __syncthreads();
#pragma unroll
    for (int m = 0; m < 32; m++) sh[m * FILT + o] = fmaxf(acc[m], 0.f);
    __syncthreads();
    int oo = o & (PDIM - 1);
    int mg = o >> 6;
    for (int m = mg * 8; m < mg * 8 + 8; m++) {
        float a = b2[oo];
        for (int i = 0; i < FILT; i++) a += sh[m * FILT + i] * w2[i * PDIM + oo];
        g_z[((size_t)(b * WW + w0 + m)) * PDIM + oo] = fmaxf(a, 0.f);
    }
}
__global__ void expand_kernel(const unsigned char* __restrict__ mask, float* __restrict__ out) {
    int b = blockIdx.y, p = blockIdx.x, o = threadIdx.x;
    const int* wc = g_wcum + b * WW;
    int lo = 0, hi = WW;
    while (lo < hi) { int mid = (lo + hi) >> 1; if (wc[mid] <= p) lo = mid + 1; else hi = mid; }
    int wid = lo; if (wid > WW - 1) wid = WW - 1;
    float v = g_z[((size_t)(b * WW + wid)) * PDIM + o];
    if (mask[b * PP + p]) v = 0.f;
    out[((size_t)(b * PP + p)) * PDIM + o] = v;
}

// ---------------- host launch -------------------------------------------------------
extern "C" void kernel_launch(void* const* d_in, const int* in_sizes, int n_in,
                              void* d_out, int out_size)
{
    const unsigned char* mask = (const unsigned char*)d_in[0];
    const float* mels = (const float*)d_in[1];
    const int* durations = (const int*)d_in[3];
    const int* wpl = (const int*)d_in[4];
    const float* c1w = (const float*)d_in[5];
    const float* c1b = (const float*)d_in[6];
    const float* l1g = (const float*)d_in[7];
    const float* l1b = (const float*)d_in[8];
    const float* c2w = (const float*)d_in[9];
    const float* c2b = (const float*)d_in[10];
    const float* l2g = (const float*)d_in[11];
    const float* l2b = (const float*)d_in[12];
    const float* w1 = (const float*)d_in[13];
    const float* b1 = (const float*)d_in[14];
    const float* w2 = (const float*)d_in[15];
    const float* b2 = (const float*)d_in[16];
    float* out = (float*)d_out;

    void *p_x1, *p_x2, *p_w1h, *p_w1m, *p_w2h, *p_w2m;
    cudaGetSymbolAddress(&p_x1, g_x1);
    cudaGetSymbolAddress(&p_x2, g_x2);
    cudaGetSymbolAddress(&p_w1h, g_w1h);
    cudaGetSymbolAddress(&p_w1m, g_w1m);
    cudaGetSymbolAddress(&p_w2h, g_w2h);
    cudaGetSymbolAddress(&p_w2m, g_w2m);

    cudaFuncSetAttribute(conv_mma<NMEL>, cudaFuncAttributeMaxDynamicSharedMemorySize, DYNSMEM);
    cudaFuncSetAttribute(conv_mma<FILT>, cudaFuncAttributeMaxDynamicSharedMemorySize, DYNSMEM);

    wsplit_kernel<NMEL><<<(KK * FILT * NMEL + 255) / 256, 256>>>(
        c1w, (__nv_bfloat16*)p_w1h, (__nv_bfloat16*)p_w1m);
    wsplit_kernel<FILT><<<(KK * FILT * FILT + 255) / 256, 256>>>(
        c2w, (__nv_bfloat16*)p_w2h, (__nv_bfloat16*)p_w2m);
    scan_kernel<<<BB, 32>>>(durations, wpl);

    dim3 cgrid(TT / BM, BB);
    conv_mma<NMEL><<<cgrid, 256, DYNSMEM>>>(
        mels, (const __nv_bfloat16*)p_w1h, (const __nv_bfloat16*)p_w1m,
        c1b, l1g, l1b, (float*)p_x1);
    conv_mma<FILT><<<cgrid, 256, DYNSMEM>>>(
        (const float*)p_x1, (const __nv_bfloat16*)p_w2h, (const __nv_bfloat16*)p_w2m,
        c2b, l2g, l2b, (float*)p_x2);

    phone_pool_kernel<<<dim3(PP, BB), FILT>>>(durations);
    word_pool_kernel<<<dim3(WW, BB), FILT>>>(wpl);
    mlp_kernel<<<dim3(WW / 32, BB), 256>>>(w1, b1, w2, b2);
    expand_kernel<<<dim3(PP, BB), PDIM>>>(mask, out);
}

// round 4
// speedup vs baseline: 2.0718x; 1.1173x over previous
#include <cuda_runtime.h>
#include <cuda_bf16.h>
#include <cstdint>

#define BB 32
#define TT 4096
#define PP 512
#define WW 128
#define NMEL 80
#define FILT 256
#define PDIM 64
#define KK 9
#define PAD 4

#define STR 40                       // smem row stride in bf16 elems (80 B, conflict-free)
#define ATILE (128 * STR)            // 5120 bf16 elems = 10240 B per tile copy
#define CONV_SMEM (2 * 4 * ATILE * 2)  // 2 bufs x (Ah,Am,Bh,Bm) x 10240 B = 81920

// ---------------- device scratch ----------------------------------------------------
__device__ __nv_bfloat16 g_melhi[(size_t)BB * TT * 96];
__device__ __nv_bfloat16 g_melmid[(size_t)BB * TT * 96];
__device__ __nv_bfloat16 g_x1hi[(size_t)BB * TT * FILT];
__device__ __nv_bfloat16 g_x1mid[(size_t)BB * TT * FILT];
__device__ float g_craw[(size_t)BB * TT * FILT];     // raw conv out (reused conv1/conv2)
__device__ float g_x2[(size_t)BB * TT * FILT];
__device__ __nv_bfloat16 g_w1h[KK * FILT * 96];
__device__ __nv_bfloat16 g_w1m[KK * FILT * 96];
__device__ __nv_bfloat16 g_w2h[KK * FILT * FILT];
__device__ __nv_bfloat16 g_w2m[KK * FILT * FILT];
__device__ float g_ph[(size_t)BB * PP * FILT];
__device__ float g_wd[(size_t)BB * WW * FILT];
__device__ float g_z [(size_t)BB * WW * PDIM];
__device__ int   g_pcum[BB * PP];
__device__ int   g_wcum[BB * WW];

// ---------------- helpers ------------------------------------------------------------
__device__ __forceinline__ uint32_t smem_u32(const void* p) {
    return (uint32_t)__cvta_generic_to_shared(p);
}
#define CP16(dst_u32, src_ptr) \
    asm volatile("cp.async.cg.shared.global [%0], [%1], 16;" :: "r"(dst_u32), "l"(src_ptr) : "memory")
#define CP_COMMIT() asm volatile("cp.async.commit_group;" ::: "memory")
#define CP_WAIT0()  asm volatile("cp.async.wait_group 0;" ::: "memory")
#define CP_WAIT1()  asm volatile("cp.async.wait_group 1;" ::: "memory")

#define MMA_BF16(d, a, b) \
    asm volatile("mma.sync.aligned.m16n8k16.row.col.f32.bf16.bf16.f32 " \
        "{%0,%1,%2,%3},{%4,%5,%6,%7},{%8,%9},{%0,%1,%2,%3};" \
        : "+f"((d)[0]), "+f"((d)[1]), "+f"((d)[2]), "+f"((d)[3]) \
        : "r"((a)[0]), "r"((a)[1]), "r"((a)[2]), "r"((a)[3]), "r"((b)[0]), "r"((b)[1]))

#define LDM4(r0, r1, r2, r3, addr) \
    asm volatile("ldmatrix.sync.aligned.m8n8.x4.shared.b16 {%0,%1,%2,%3}, [%4];" \
        : "=r"(r0), "=r"(r1), "=r"(r2), "=r"(r3) : "r"(addr))

__device__ __forceinline__ uint32_t pack_hi2(float x0, float x1) {
    __nv_bfloat162 t(__float2bfloat16_rn(x0), __float2bfloat16_rn(x1));
    return *reinterpret_cast<uint32_t*>(&t);
}
__device__ __forceinline__ uint32_t pack_mid2(float x0, float x1) {
    float h0 = __bfloat162float(__float2bfloat16_rn(x0));
    float h1 = __bfloat162float(__float2bfloat16_rn(x1));
    __nv_bfloat162 t(__float2bfloat16_rn(x0 - h0), __float2bfloat16_rn(x1 - h1));
    return *reinterpret_cast<uint32_t*>(&t);
}

// ---------------- prep kernels -------------------------------------------------------
__global__ void mel_split_kernel(const float* __restrict__ mels) {
    size_t i = (size_t)blockIdx.x * blockDim.x + threadIdx.x;
    if (i < (size_t)BB * TT * 96) {
        size_t t = i / 96;
        int ci = (int)(i % 96);
        float x = (ci < NMEL) ? mels[t * NMEL + ci] : 0.f;
        __nv_bfloat16 h = __float2bfloat16_rn(x);
        g_melhi[i] = h;
        g_melmid[i] = __float2bfloat16_rn(x - __bfloat162float(h));
    }
}
template <int CIN, int CINP>
__global__ void wsplit_kernel(const float* __restrict__ w,
                              __nv_bfloat16* __restrict__ wh,
                              __nv_bfloat16* __restrict__ wm) {
    int i = blockIdx.x * blockDim.x + threadIdx.x;      // [tap][co][ci-padded]
    if (i < KK * FILT * CINP) {
        int ci = i % CINP;
        int co = (i / CINP) % FILT;
        int tap = i / (CINP * FILT);
        float x = (ci < CIN) ? w[(co * CIN + ci) * KK + tap] : 0.f;
        __nv_bfloat16 h = __float2bfloat16_rn(x);
        wh[i] = h;
        wm[i] = __float2bfloat16_rn(x - __bfloat162float(h));
    }
}
__global__ void scan_kernel(const int* __restrict__ dur, const int* __restrict__ wpl) {
    int b = blockIdx.x;
    if (threadIdx.x == 0) {
        int s = 0;
        for (int p = 0; p < PP; p++) { s += dur[b * PP + p]; g_pcum[b * PP + p] = s; }
        s = 0;
        for (int w = 0; w < WW; w++) { s += wpl[b * WW + w]; g_wcum[b * WW + w] = s; }
    }
}

// ---------------- conv via bf16x3 mma.sync, tile 128x128, 2 CTAs/SM ------------------
template <int KCH>     // k32 chunks per tap: conv1=3 (cin padded 96), conv2=8
__global__ void __launch_bounds__(256, 2) conv_mma(
    const __nv_bfloat16* __restrict__ Ahi, const __nv_bfloat16* __restrict__ Amid,
    const __nv_bfloat16* __restrict__ Bhi, const __nv_bfloat16* __restrict__ Bmid,
    float* __restrict__ outc)
{
    constexpr int CINP = KCH * 32;
    constexpr int NST = KK * KCH;
    extern __shared__ __nv_bfloat16 smbf[];

    const int tid = threadIdx.x;
    const int wid = tid >> 5, lane = tid & 31;
    const int wm = wid & 1, wn = wid >> 1;              // 2m x 4n warps
    const int t0 = blockIdx.x * 128;
    const int n0 = blockIdx.y * 128;
    const int b = blockIdx.z;
    const size_t bT = (size_t)b * TT;

    float acc[4][4][4];
#pragma unroll
    for (int mt = 0; mt < 4; mt++)
#pragma unroll
        for (int nt = 0; nt < 4; nt++)
#pragma unroll
            for (int q = 0; q < 4; q++) acc[mt][nt][q] = 0.f;

    // ldmatrix lane-invariant offsets (bytes)
    const int a_l = ((lane >> 3) & 1) * 8 + (lane & 7);
    const int a_k = (lane >> 4) * 8;
    const int b_l = (lane >> 4) * 8 + (lane & 7);
    const int b_k = ((lane >> 3) & 1) * 8;
    uint32_t aoff[4], boff[2];
#pragma unroll
    for (int mt = 0; mt < 4; mt++)
        aoff[mt] = ((wm * 64 + mt * 16 + a_l) * STR + a_k) * 2;
#pragma unroll
    for (int np = 0; np < 2; np++)
        boff[np] = ((wn * 32 + np * 16 + b_l) * STR + b_k) * 2;

    const int c0 = (tid & 3) * 8;           // chunk col (bf16 elems) within k32
    const int r0a = tid >> 2;               // rows 0..63; +64 for second pass

    auto load_stage = [&](int s, int buf) {
        int tap = s / KCH, ci0 = (s - tap * KCH) * 32;
        __nv_bfloat16* sA = smbf + buf * 4 * ATILE;
        __nv_bfloat16* sB = sA + 2 * ATILE;
        const uint4 zz = make_uint4(0, 0, 0, 0);
#pragma unroll
        for (int i = 0; i < 2; i++) {
            int row = r0a + i * 64;
            // ---- A (with halo OOB zero-fill) ----
            int trow = t0 + row + tap - PAD;
            __nv_bfloat16* dA = sA + row * STR + c0;
            if (trow >= 0 && trow < TT) {
                const __nv_bfloat16* s1 = Ahi + (bT + trow) * CINP + ci0 + c0;
                const __nv_bfloat16* s2 = Amid + (bT + trow) * CINP + ci0 + c0;
                CP16(smem_u32(dA), s1);
                CP16(smem_u32(dA + ATILE), s2);
            } else {
                *(uint4*)dA = zz;
                *(uint4*)(dA + ATILE) = zz;
            }
            // ---- B (never OOB) ----
            const __nv_bfloat16* w1 = Bhi + ((size_t)tap * FILT + n0 + row) * CINP + ci0 + c0;
            const __nv_bfloat16* w2 = Bmid + ((size_t)tap * FILT + n0 + row) * CINP + ci0 + c0;
            __nv_bfloat16* dB = sB + row * STR + c0;
            CP16(smem_u32(dB), w1);
            CP16(smem_u32(dB + ATILE), w2);
        }
    };

    load_stage(0, 0);
    CP_COMMIT();

    for (int s = 0; s < NST; s++) {
        int buf = s & 1;
        if (s + 1 < NST) { load_stage(s + 1, buf ^ 1); CP_COMMIT(); CP_WAIT1(); }
        else CP_WAIT0();
        __syncthreads();

        uint32_t aAh = smem_u32(smbf + buf * 4 * ATILE);
        uint32_t aAm = aAh + ATILE * 2;
        uint32_t aBh = aAh + 4 * ATILE;   // bytes: 2*ATILE elems * 2
        uint32_t aBm = aAh + 6 * ATILE;

#pragma unroll
        for (int kk = 0; kk < 2; kk++) {
            uint32_t ah[4][4], bh[4][2], bm[4][2];
#pragma unroll
            for (int mt = 0; mt < 4; mt++)
                LDM4(ah[mt][0], ah[mt][1], ah[mt][2], ah[mt][3], aAh + aoff[mt] + kk * 32);
#pragma unroll
            for (int np = 0; np < 2; np++)
                LDM4(bh[2 * np][0], bh[2 * np][1], bh[2 * np + 1][0], bh[2 * np + 1][1],
                     aBh + boff[np] + kk * 32);
#pragma unroll
            for (int mt = 0; mt < 4; mt++)
#pragma unroll
                for (int nt = 0; nt < 4; nt++) MMA_BF16(acc[mt][nt], ah[mt], bh[nt]);

#pragma unroll
            for (int np = 0; np < 2; np++)
                LDM4(bm[2 * np][0], bm[2 * np][1], bm[2 * np + 1][0], bm[2 * np + 1][1],
                     aBm + boff[np] + kk * 32);
#pragma unroll
            for (int mt = 0; mt < 4; mt++)
#pragma unroll
                for (int nt = 0; nt < 4; nt++) MMA_BF16(acc[mt][nt], ah[mt], bm[nt]);

#pragma unroll
            for (int mt = 0; mt < 4; mt++)
                LDM4(ah[mt][0], ah[mt][1], ah[mt][2], ah[mt][3], aAm + aoff[mt] + kk * 32);
#pragma unroll
            for (int mt = 0; mt < 4; mt++)
#pragma unroll
                for (int nt = 0; nt < 4; nt++) MMA_BF16(acc[mt][nt], ah[mt], bh[nt]);
        }
        __syncthreads();
    }

    // ---------------- epilogue: stage to smem, coalesced store ----------------------
    float* st = (float*)smbf;                 // 64 KB staging
    const int r = lane >> 2, cq = lane & 3;
#pragma unroll
    for (int mt = 0; mt < 4; mt++) {
        int R0 = wm * 64 + mt * 16 + r;
#pragma unroll
        for (int nt = 0; nt < 4; nt++) {
            int C = wn * 32 + nt * 8 + 2 * cq;
            st[R0 * 128 + C]           = acc[mt][nt][0];
            st[R0 * 128 + C + 1]       = acc[mt][nt][1];
            st[(R0 + 8) * 128 + C]     = acc[mt][nt][2];
            st[(R0 + 8) * 128 + C + 1] = acc[mt][nt][3];
        }
    }
    __syncthreads();
#pragma unroll
    for (int i = 0; i < 16; i++) {
        int f4 = tid + i * 256;               // 4096 float4 = 128x128
        int row = f4 >> 5, c4 = f4 & 31;
        *(float4*)(outc + (bT + t0 + row) * FILT + n0 + c4 * 4) = ((float4*)st)[f4];
    }
}

// ---------------- bias + relu + LN pass (warp per frame) ----------------------------
// MODE 0: write bf16 hi/mid split.  MODE 1: write fp32.
template <int MODE>
__global__ void __launch_bounds__(256) ln_kernel(
    const float* __restrict__ gc,
    const float* __restrict__ bias, const float* __restrict__ gamma,
    const float* __restrict__ beta,
    float* __restrict__ outf,
    __nv_bfloat16* __restrict__ outh, __nv_bfloat16* __restrict__ outm)
{
    __shared__ float sB[FILT], sG[FILT], sE[FILT];
    int tid = threadIdx.x;
    if (tid < FILT) { sB[tid] = bias[tid]; sG[tid] = gamma[tid]; sE[tid] = beta[tid]; }
    __syncthreads();

    int wid = tid >> 5, lane = tid & 31;
    size_t frame = (size_t)blockIdx.x * 8 + wid;
    const float4* rp = (const float4*)(gc + frame * FILT);
    float4 v0 = rp[lane], v1 = rp[lane + 32];
    int ca = lane * 4, cb = 128 + lane * 4;

    float x[8];
    x[0] = fmaxf(v0.x + sB[ca], 0.f);     x[1] = fmaxf(v0.y + sB[ca + 1], 0.f);
    x[2] = fmaxf(v0.z + sB[ca + 2], 0.f); x[3] = fmaxf(v0.w + sB[ca + 3], 0.f);
    x[4] = fmaxf(v1.x + sB[cb], 0.f);     x[5] = fmaxf(v1.y + sB[cb + 1], 0.f);
    x[6] = fmaxf(v1.z + sB[cb + 2], 0.f); x[7] = fmaxf(v1.w + sB[cb + 3], 0.f);

    float s = 0.f, q = 0.f;
#pragma unroll
    for (int j = 0; j < 8; j++) { s += x[j]; q += x[j] * x[j]; }
#pragma unroll
    for (int off = 16; off > 0; off >>= 1) {
        s += __shfl_xor_sync(0xffffffffu, s, off);
        q += __shfl_xor_sync(0xffffffffu, q, off);
    }
    float m = s * (1.f / FILT);
    float rs = rsqrtf(q * (1.f / FILT) - m * m + 1e-5f);

    float y[8];
#pragma unroll
    for (int j = 0; j < 4; j++) y[j] = (x[j] - m) * rs * sG[ca + j] + sE[ca + j];
#pragma unroll
    for (int j = 0; j < 4; j++) y[4 + j] = (x[4 + j] - m) * rs * sG[cb + j] + sE[cb + j];

    if (MODE == 1) {
        float4* wp = (float4*)(outf + frame * FILT);
        wp[lane] = make_float4(y[0], y[1], y[2], y[3]);
        wp[lane + 32] = make_float4(y[4], y[5], y[6], y[7]);
    } else {
        uint2* hp = (uint2*)(outh + frame * FILT);
        uint2* mp = (uint2*)(outm + frame * FILT);
        hp[lane]      = make_uint2(pack_hi2(y[0], y[1]), pack_hi2(y[2], y[3]));
        hp[lane + 32] = make_uint2(pack_hi2(y[4], y[5]), pack_hi2(y[6], y[7]));
        mp[lane]      = make_uint2(pack_mid2(y[0], y[1]), pack_mid2(y[2], y[3]));
        mp[lane + 32] = make_uint2(pack_mid2(y[4], y[5]), pack_mid2(y[6], y[7]));
    }
}

// ---------------- pooling / mlp / expand (validated round 1) ------------------------
__global__ void phone_pool_kernel(const int* __restrict__ dur) {
    int b = blockIdx.y, p = blockIdx.x, c = threadIdx.x;
    int start = p ? g_pcum[b * PP + p - 1] : 0;
    int end = g_pcum[b * PP + p];
    if (start > TT) start = TT;
    if (end > TT) end = TT;
    float s = 0.f;
    for (int t = start; t < end; t++) s += g_x2[((size_t)(b * TT + t)) * FILT + c];
    int d = dur[b * PP + p]; if (d < 1) d = 1;
    g_ph[((size_t)(b * PP + p)) * FILT + c] = s / (float)d;
}
__global__ void word_pool_kernel(const int* __restrict__ wpl) {
    int b = blockIdx.y, w = blockIdx.x, c = threadIdx.x;
    int start = w ? g_wcum[b * WW + w - 1] : 0;
    int end = g_wcum[b * WW + w];
    if (start > PP) start = PP;
    if (end > PP) end = PP;
    float s = 0.f;
    for (int p = start; p < end; p++) s += g_ph[((size_t)(b * PP + p)) * FILT + c];
    int d = wpl[b * WW + w]; if (d < 1) d = 1;
    g_wd[((size_t)(b * WW + w)) * FILT + c] = s / (float)d;
}
__global__ void __launch_bounds__(256) mlp_kernel(
    const float* __restrict__ w1, const float* __restrict__ b1,
    const float* __restrict__ w2, const float* __restrict__ b2)
{
    __shared__ float sh[32 * FILT];
    int b = blockIdx.y, w0 = blockIdx.x * 32, o = threadIdx.x;
    for (int idx = o; idx < 32 * FILT; idx += 256)
        sh[idx] = g_wd[((size_t)(b * WW + w0)) * FILT + idx];
    __syncthreads();
    float acc[32];
    float bv = b1[o];
#pragma unroll
    for (int m = 0; m < 32; m++) acc[m] = bv;
    for (int i = 0; i < FILT; i++) {
        float wv = w1[i * FILT + o];
#pragma unroll
        for (int m = 0; m < 32; m++) acc[m] += sh[m * FILT + i] * wv;
    }
    __syncthreads();
#pragma unroll
    for (int m = 0; m < 32; m++) sh[m * FILT + o] = fmaxf(acc[m], 0.f);
    __syncthreads();
    int oo = o & (PDIM - 1);
    int mg = o >> 6;
    for (int m = mg * 8; m < mg * 8 + 8; m++) {
        float a = b2[oo];
        for (int i = 0; i < FILT; i++) a += sh[m * FILT + i] * w2[i * PDIM + oo];
        g_z[((size_t)(b * WW + w0 + m)) * PDIM + oo] = fmaxf(a, 0.f);
    }
}
__global__ void expand_kernel(const unsigned char* __restrict__ mask, float* __restrict__ out) {
    int b = blockIdx.y, p = blockIdx.x, o = threadIdx.x;
    const int* wc = g_wcum + b * WW;
    int lo = 0, hi = WW;
    while (lo < hi) { int mid = (lo + hi) >> 1; if (wc[mid] <= p) lo = mid + 1; else hi = mid; }
    int wid = lo; if (wid > WW - 1) wid = WW - 1;
    float v = g_z[((size_t)(b * WW + wid)) * PDIM + o];
    if (mask[b * PP + p]) v = 0.f;
    out[((size_t)(b * PP + p)) * PDIM + o] = v;
}

// ---------------- host launch -------------------------------------------------------
extern "C" void kernel_launch(void* const* d_in, const int* in_sizes, int n_in,
                              void* d_out, int out_size)
{
    const unsigned char* mask = (const unsigned char*)d_in[0];
    const float* mels = (const float*)d_in[1];
    const int* durations = (const int*)d_in[3];
    const int* wpl = (const int*)d_in[4];
    const float* c1w = (const float*)d_in[5];
    const float* c1b = (const float*)d_in[6];
    const float* l1g = (const float*)d_in[7];
    const float* l1b = (const float*)d_in[8];
    const float* c2w = (const float*)d_in[9];
    const float* c2b = (const float*)d_in[10];
    const float* l2g = (const float*)d_in[11];
    const float* l2b = (const float*)d_in[12];
    const float* w1 = (const float*)d_in[13];
    const float* b1 = (const float*)d_in[14];
    const float* w2 = (const float*)d_in[15];
    const float* b2 = (const float*)d_in[16];
    float* out = (float*)d_out;

    void *p_melhi, *p_melmid, *p_x1hi, *p_x1mid, *p_craw, *p_x2;
    void *p_w1h, *p_w1m, *p_w2h, *p_w2m;
    cudaGetSymbolAddress(&p_melhi, g_melhi);
    cudaGetSymbolAddress(&p_melmid, g_melmid);
    cudaGetSymbolAddress(&p_x1hi, g_x1hi);
    cudaGetSymbolAddress(&p_x1mid, g_x1mid);
    cudaGetSymbolAddress(&p_craw, g_craw);
    cudaGetSymbolAddress(&p_x2, g_x2);
    cudaGetSymbolAddress(&p_w1h, g_w1h);
    cudaGetSymbolAddress(&p_w1m, g_w1m);
    cudaGetSymbolAddress(&p_w2h, g_w2h);
    cudaGetSymbolAddress(&p_w2m, g_w2m);

    cudaFuncSetAttribute(conv_mma<3>, cudaFuncAttributeMaxDynamicSharedMemorySize, CONV_SMEM);
    cudaFuncSetAttribute(conv_mma<8>, cudaFuncAttributeMaxDynamicSharedMemorySize, CONV_SMEM);

    mel_split_kernel<<<(int)(((size_t)BB * TT * 96 + 255) / 256), 256>>>(mels);
    wsplit_kernel<NMEL, 96><<<(KK * FILT * 96 + 255) / 256, 256>>>(
        c1w, (__nv_bfloat16*)p_w1h, (__nv_bfloat16*)p_w1m);
    wsplit_kernel<FILT, FILT><<<(KK * FILT * FILT + 255) / 256, 256>>>(
        c2w, (__nv_bfloat16*)p_w2h, (__nv_bfloat16*)p_w2m);
    scan_kernel<<<BB, 32>>>(durations, wpl);

    dim3 cgrid(TT / 128, 2, BB);
    conv_mma<3><<<cgrid, 256, CONV_SMEM>>>(
        (const __nv_bfloat16*)p_melhi, (const __nv_bfloat16*)p_melmid,
        (const __nv_bfloat16*)p_w1h, (const __nv_bfloat16*)p_w1m, (float*)p_craw);
    ln_kernel<0><<<BB * TT / 8, 256>>>((const float*)p_craw, c1b, l1g, l1b,
        nullptr, (__nv_bfloat16*)p_x1hi, (__nv_bfloat16*)p_x1mid);
    conv_mma<8><<<cgrid, 256, CONV_SMEM>>>(
        (const __nv_bfloat16*)p_x1hi, (const __nv_bfloat16*)p_x1mid,
        (const __nv_bfloat16*)p_w2h, (const __nv_bfloat16*)p_w2m, (float*)p_craw);
    ln_kernel<1><<<BB * TT / 8, 256>>>((const float*)p_craw, c2b, l2g, l2b,
        (float*)p_x2, nullptr, nullptr);

    phone_pool_kernel<<<dim3(PP, BB), FILT>>>(durations);
    word_pool_kernel<<<dim3(WW, BB), FILT>>>(wpl);
    mlp_kernel<<<dim3(WW / 32, BB), 256>>>(w1, b1, w2, b2);
    expand_kernel<<<dim3(PP, BB), PDIM>>>(mask, out);
}

// round 5
// speedup vs baseline: 2.4051x; 1.1609x over previous
#include <cuda_runtime.h>
#include <cuda_bf16.h>
#include <cstdint>

#define BB 32
#define TT 4096
#define PP 512
#define WW 128
#define NMEL 80
#define FILT 256
#define PDIM 64
#define KK 9
#define PAD 4

#define STR 40                        // smem row stride (bf16), conflict-free
#define A_ROWS 136                    // 128 + 2*PAD halo
#define A_CP 5440                     // A_ROWS*STR elems per copy
#define B_CP 5120                     // 128*STR elems per copy
// elem offsets: A0h=0 A0m=5440 A1h=10880 A1m=16320 | B0h=21760 B0m=26880 B1h=32000 B1m=37120
#define OFF_B 21760
#define CONV_SMEM ((OFF_B + 2 * 2 * B_CP) * 2)    // 84480 bytes

// ---------------- device scratch ----------------------------------------------------
__device__ __nv_bfloat16 g_melhi[(size_t)BB * TT * 96];
__device__ __nv_bfloat16 g_melmid[(size_t)BB * TT * 96];
__device__ __nv_bfloat16 g_x1hi[(size_t)BB * TT * FILT];
__device__ __nv_bfloat16 g_x1mid[(size_t)BB * TT * FILT];
__device__ float g_craw[(size_t)BB * TT * FILT];
__device__ float g_x2[(size_t)BB * TT * FILT];
__device__ __nv_bfloat16 g_w1h[KK * FILT * 96];
__device__ __nv_bfloat16 g_w1m[KK * FILT * 96];
__device__ __nv_bfloat16 g_w2h[KK * FILT * FILT];
__device__ __nv_bfloat16 g_w2m[KK * FILT * FILT];
__device__ float g_ph[(size_t)BB * PP * FILT];
__device__ float g_wd[(size_t)BB * WW * FILT];
__device__ float g_z [(size_t)BB * WW * PDIM];
__device__ int   g_pcum[BB * PP];
__device__ int   g_wcum[BB * WW];

// ---------------- helpers ------------------------------------------------------------
__device__ __forceinline__ uint32_t smem_u32(const void* p) {
    return (uint32_t)__cvta_generic_to_shared(p);
}
#define CP16(dst_u32, src_ptr) \
    asm volatile("cp.async.cg.shared.global [%0], [%1], 16;" :: "r"(dst_u32), "l"(src_ptr) : "memory")
#define CP_COMMIT() asm volatile("cp.async.commit_group;" ::: "memory")
#define CP_WAIT0()  asm volatile("cp.async.wait_group 0;" ::: "memory")

#define MMA_BF16(d, a, b) \
    asm volatile("mma.sync.aligned.m16n8k16.row.col.f32.bf16.bf16.f32 " \
        "{%0,%1,%2,%3},{%4,%5,%6,%7},{%8,%9},{%0,%1,%2,%3};" \
        : "+f"((d)[0]), "+f"((d)[1]), "+f"((d)[2]), "+f"((d)[3]) \
        : "r"((a)[0]), "r"((a)[1]), "r"((a)[2]), "r"((a)[3]), "r"((b)[0]), "r"((b)[1]))

#define LDM4(r0, r1, r2, r3, addr) \
    asm volatile("ldmatrix.sync.aligned.m8n8.x4.shared.b16 {%0,%1,%2,%3}, [%4];" \
        : "=r"(r0), "=r"(r1), "=r"(r2), "=r"(r3) : "r"(addr))

__device__ __forceinline__ uint32_t pack_hi2(float x0, float x1) {
    __nv_bfloat162 t(__float2bfloat16_rn(x0), __float2bfloat16_rn(x1));
    return *reinterpret_cast<uint32_t*>(&t);
}
__device__ __forceinline__ uint32_t pack_mid2(float x0, float x1) {
    float h0 = __bfloat162float(__float2bfloat16_rn(x0));
    float h1 = __bfloat162float(__float2bfloat16_rn(x1));
    __nv_bfloat162 t(__float2bfloat16_rn(x0 - h0), __float2bfloat16_rn(x1 - h1));
    return *reinterpret_cast<uint32_t*>(&t);
}

// ---------------- prep kernels -------------------------------------------------------
__global__ void mel_split_kernel(const float* __restrict__ mels) {
    size_t i = (size_t)blockIdx.x * blockDim.x + threadIdx.x;
    if (i < (size_t)BB * TT * 96) {
        size_t t = i / 96;
        int ci = (int)(i % 96);
        float x = (ci < NMEL) ? mels[t * NMEL + ci] : 0.f;
        __nv_bfloat16 h = __float2bfloat16_rn(x);
        g_melhi[i] = h;
        g_melmid[i] = __float2bfloat16_rn(x - __bfloat162float(h));
    }
}
template <int CIN, int CINP>
__global__ void wsplit_kernel(const float* __restrict__ w,
                              __nv_bfloat16* __restrict__ wh,
                              __nv_bfloat16* __restrict__ wm) {
    int i = blockIdx.x * blockDim.x + threadIdx.x;      // [tap][co][ci-padded]
    if (i < KK * FILT * CINP) {
        int ci = i % CINP;
        int co = (i / CINP) % FILT;
        int tap = i / (CINP * FILT);
        float x = (ci < CIN) ? w[(co * CIN + ci) * KK + tap] : 0.f;
        __nv_bfloat16 h = __float2bfloat16_rn(x);
        wh[i] = h;
        wm[i] = __float2bfloat16_rn(x - __bfloat162float(h));
    }
}
__global__ void scan_kernel(const int* __restrict__ dur, const int* __restrict__ wpl) {
    int b = blockIdx.x, lane = threadIdx.x;             // 32 threads/block
    // phones: 16 per lane
    int v[16], s = 0;
#pragma unroll
    for (int i = 0; i < 16; i++) { v[i] = dur[b * PP + lane * 16 + i]; s += v[i]; }
    int inc = s;
#pragma unroll
    for (int off = 1; off < 32; off <<= 1) {
        int t = __shfl_up_sync(0xffffffffu, inc, off);
        if (lane >= off) inc += t;
    }
    int base = inc - s, run = 0;
#pragma unroll
    for (int i = 0; i < 16; i++) { run += v[i]; g_pcum[b * PP + lane * 16 + i] = base + run; }
    // words: 4 per lane
    int w[4]; s = 0;
#pragma unroll
    for (int i = 0; i < 4; i++) { w[i] = wpl[b * WW + lane * 4 + i]; s += w[i]; }
    inc = s;
#pragma unroll
    for (int off = 1; off < 32; off <<= 1) {
        int t = __shfl_up_sync(0xffffffffu, inc, off);
        if (lane >= off) inc += t;
    }
    base = inc - s; run = 0;
#pragma unroll
    for (int i = 0; i < 4; i++) { run += w[i]; g_wcum[b * WW + lane * 4 + i] = base + run; }
}

// ---------------- conv via bf16x3 mma.sync, halo-resident A, 2 CTAs/SM ---------------
template <int NCH>     // cin chunks of 32: conv1=3 (padded 96), conv2=8
__global__ void __launch_bounds__(256, 2) conv_mma(
    const __nv_bfloat16* __restrict__ Ahi, const __nv_bfloat16* __restrict__ Amid,
    const __nv_bfloat16* __restrict__ Bhi, const __nv_bfloat16* __restrict__ Bmid,
    float* __restrict__ outc)
{
    constexpr int CINP = NCH * 32;
    constexpr int NST = NCH * KK;
    extern __shared__ __nv_bfloat16 smbf[];

    const int tid = threadIdx.x;
    const int wid = tid >> 5, lane = tid & 31;
    const int wm = wid & 1, wn = wid >> 1;              // 2m x 4n warps
    const int t0 = blockIdx.x * 128;
    const int n0 = blockIdx.y * 128;
    const size_t bT = (size_t)blockIdx.z * TT;
    const uint32_t smb = smem_u32(smbf);

    float acc[4][4][4];
#pragma unroll
    for (int mt = 0; mt < 4; mt++)
#pragma unroll
        for (int nt = 0; nt < 4; nt++)
#pragma unroll
            for (int q = 0; q < 4; q++) acc[mt][nt][q] = 0.f;

    // ldmatrix lane offsets
    const int a_l = ((lane >> 3) & 1) * 8 + (lane & 7);
    const int a_k = (lane >> 4) * 8;
    const int b_l = (lane >> 4) * 8 + (lane & 7);
    const int b_k = ((lane >> 3) & 1) * 8;
    uint32_t aoff[4], boff[2];
#pragma unroll
    for (int mt = 0; mt < 4; mt++)
        aoff[mt] = ((wm * 64 + mt * 16 + a_l) * STR + a_k) * 2;
#pragma unroll
    for (int np = 0; np < 2; np++)
        boff[np] = ((wn * 32 + np * 16 + b_l) * STR + b_k) * 2;

    auto issue_loads = [&](int s) {
        int chunk = s / KK, tap = s - chunk * KK;
        __nv_bfloat16* sB = smbf + OFF_B + (s & 1) * (2 * B_CP);
#pragma unroll
        for (int j = 0; j < 4; j++) {
            int q = tid + j * 256;                      // 0..1023
            int copy = q >> 9, rc = q & 511;
            int row = rc >> 2, c16 = rc & 3;
            const __nv_bfloat16* src = (copy ? Bmid : Bhi)
                + ((size_t)tap * FILT + n0 + row) * CINP + chunk * 32 + c16 * 8;
            CP16(smem_u32(sB + copy * B_CP + row * STR + c16 * 8), src);
        }
        if (tap == 0) {
            __nv_bfloat16* sA = smbf + (chunk & 1) * (2 * A_CP);
#pragma unroll
            for (int j = 0; j < 5; j++) {
                int q = tid + j * 256;
                if (q < 1088) {
                    int copy = (q >= 544) ? 1 : 0;
                    int rem = q - copy * 544;
                    int row = rem >> 2, c16 = rem & 3;
                    int trow = t0 + row - PAD;
                    __nv_bfloat16* dst = sA + copy * A_CP + row * STR + c16 * 8;
                    if (trow >= 0 && trow < TT) {
                        const __nv_bfloat16* src = (copy ? Amid : Ahi)
                            + (bT + trow) * CINP + chunk * 32 + c16 * 8;
                        CP16(smem_u32(dst), src);
                    } else {
                        *(uint4*)dst = make_uint4(0, 0, 0, 0);
                    }
                }
            }
        }
    };

    issue_loads(0);
    CP_COMMIT();

    for (int s = 0; s < NST; s++) {
        CP_WAIT0();
        __syncthreads();
        if (s + 1 < NST) { issue_loads(s + 1); CP_COMMIT(); }

        int chunk = s / KK, tap = s - chunk * KK;
        uint32_t aAh = smb + (chunk & 1) * (2 * A_CP * 2) + tap * (STR * 2);
        uint32_t aAm = aAh + A_CP * 2;
        uint32_t aBh = smb + (OFF_B + (s & 1) * (2 * B_CP)) * 2;
        uint32_t aBm = aBh + B_CP * 2;

#pragma unroll
        for (int kk = 0; kk < 2; kk++) {
            uint32_t ah[4][4], bh[4][2], bm[4][2];
#pragma unroll
            for (int mt = 0; mt < 4; mt++)
                LDM4(ah[mt][0], ah[mt][1], ah[mt][2], ah[mt][3], aAh + aoff[mt] + kk * 32);
#pragma unroll
            for (int np = 0; np < 2; np++)
                LDM4(bh[2 * np][0], bh[2 * np][1], bh[2 * np + 1][0], bh[2 * np + 1][1],
                     aBh + boff[np] + kk * 32);
#pragma unroll
            for (int mt = 0; mt < 4; mt++)
#pragma unroll
                for (int nt = 0; nt < 4; nt++) MMA_BF16(acc[mt][nt], ah[mt], bh[nt]);

#pragma unroll
            for (int np = 0; np < 2; np++)
                LDM4(bm[2 * np][0], bm[2 * np][1], bm[2 * np + 1][0], bm[2 * np + 1][1],
                     aBm + boff[np] + kk * 32);
#pragma unroll
            for (int mt = 0; mt < 4; mt++)
#pragma unroll
                for (int nt = 0; nt < 4; nt++) MMA_BF16(acc[mt][nt], ah[mt], bm[nt]);

#pragma unroll
            for (int mt = 0; mt < 4; mt++)
                LDM4(ah[mt][0], ah[mt][1], ah[mt][2], ah[mt][3], aAm + aoff[mt] + kk * 32);
#pragma unroll
            for (int mt = 0; mt < 4; mt++)
#pragma unroll
                for (int nt = 0; nt < 4; nt++) MMA_BF16(acc[mt][nt], ah[mt], bh[nt]);
        }
    }
    __syncthreads();

    // ---------------- epilogue: stage to smem, coalesced store ----------------------
    float* st = (float*)smbf;                 // 64 KB staging (fits in 84.5 KB)
    const int r = lane >> 2, cq = lane & 3;
#pragma unroll
    for (int mt = 0; mt < 4; mt++) {
        int R0 = wm * 64 + mt * 16 + r;
#pragma unroll
        for (int nt = 0; nt < 4; nt++) {
            int C = wn * 32 + nt * 8 + 2 * cq;
            st[R0 * 128 + C]           = acc[mt][nt][0];
            st[R0 * 128 + C + 1]       = acc[mt][nt][1];
            st[(R0 + 8) * 128 + C]     = acc[mt][nt][2];
            st[(R0 + 8) * 128 + C + 1] = acc[mt][nt][3];
        }
    }
    __syncthreads();
#pragma unroll
    for (int i = 0; i < 16; i++) {
        int f4 = tid + i * 256;               // 4096 float4 = 128x128
        int row = f4 >> 5, c4 = f4 & 31;
        *(float4*)(outc + (bT + t0 + row) * FILT + n0 + c4 * 4) = ((float4*)st)[f4];
    }
}

// ---------------- bias + relu + LN pass (warp per frame) ----------------------------
template <int MODE>    // 0: write bf16 hi/mid.  1: write fp32
__global__ void __launch_bounds__(256) ln_kernel(
    const float* __restrict__ gc,
    const float* __restrict__ bias, const float* __restrict__ gamma,
    const float* __restrict__ beta,
    float* __restrict__ outf,
    __nv_bfloat16* __restrict__ outh, __nv_bfloat16* __restrict__ outm)
{
    __shared__ float sB[FILT], sG[FILT], sE[FILT];
    int tid = threadIdx.x;
    if (tid < FILT) { sB[tid] = bias[tid]; sG[tid] = gamma[tid]; sE[tid] = beta[tid]; }
    __syncthreads();

    int wid = tid >> 5, lane = tid & 31;
    size_t frame = (size_t)blockIdx.x * 8 + wid;
    const float4* rp = (const float4*)(gc + frame * FILT);
    float4 v0 = rp[lane], v1 = rp[lane + 32];
    int ca = lane * 4, cb = 128 + lane * 4;

    float x[8];
    x[0] = fmaxf(v0.x + sB[ca], 0.f);     x[1] = fmaxf(v0.y + sB[ca + 1], 0.f);
    x[2] = fmaxf(v0.z + sB[ca + 2], 0.f); x[3] = fmaxf(v0.w + sB[ca + 3], 0.f);
    x[4] = fmaxf(v1.x + sB[cb], 0.f);     x[5] = fmaxf(v1.y + sB[cb + 1], 0.f);
    x[6] = fmaxf(v1.z + sB[cb + 2], 0.f); x[7] = fmaxf(v1.w + sB[cb + 3], 0.f);

    float s = 0.f, q = 0.f;
#pragma unroll
    for (int j = 0; j < 8; j++) { s += x[j]; q += x[j] * x[j]; }
#pragma unroll
    for (int off = 16; off > 0; off >>= 1) {
        s += __shfl_xor_sync(0xffffffffu, s, off);
        q += __shfl_xor_sync(0xffffffffu, q, off);
    }
    float m = s * (1.f / FILT);
    float rs = rsqrtf(q * (1.f / FILT) - m * m + 1e-5f);

    float y[8];
#pragma unroll
    for (int j = 0; j < 4; j++) y[j] = (x[j] - m) * rs * sG[ca + j] + sE[ca + j];
#pragma unroll
    for (int j = 0; j < 4; j++) y[4 + j] = (x[4 + j] - m) * rs * sG[cb + j] + sE[cb + j];

    if (MODE == 1) {
        float4* wp = (float4*)(outf + frame * FILT);
        wp[lane] = make_float4(y[0], y[1], y[2], y[3]);
        wp[lane + 32] = make_float4(y[4], y[5], y[6], y[7]);
    } else {
        uint2* hp = (uint2*)(outh + frame * FILT);
        uint2* mp = (uint2*)(outm + frame * FILT);
        hp[lane]      = make_uint2(pack_hi2(y[0], y[1]), pack_hi2(y[2], y[3]));
        hp[lane + 32] = make_uint2(pack_hi2(y[4], y[5]), pack_hi2(y[6], y[7]));
        mp[lane]      = make_uint2(pack_mid2(y[0], y[1]), pack_mid2(y[2], y[3]));
        mp[lane + 32] = make_uint2(pack_mid2(y[4], y[5]), pack_mid2(y[6], y[7]));
    }
}

// ---------------- pooling / mlp / expand --------------------------------------------
__global__ void phone_pool_kernel(const int* __restrict__ dur) {
    int b = blockIdx.y, p = blockIdx.x, c = threadIdx.x;
    int start = p ? g_pcum[b * PP + p - 1] : 0;
    int end = g_pcum[b * PP + p];
    if (start > TT) start = TT;
    if (end > TT) end = TT;
    float s = 0.f;
    for (int t = start; t < end; t++) s += g_x2[((size_t)(b * TT + t)) * FILT + c];
    int d = dur[b * PP + p]; if (d < 1) d = 1;
    g_ph[((size_t)(b * PP + p)) * FILT + c] = s / (float)d;
}
__global__ void word_pool_kernel(const int* __restrict__ wpl) {
    int b = blockIdx.y, w = blockIdx.x, c = threadIdx.x;
    int start = w ? g_wcum[b * WW + w - 1] : 0;
    int end = g_wcum[b * WW + w];
    if (start > PP) start = PP;
    if (end > PP) end = PP;
    float s = 0.f;
    for (int p = start; p < end; p++) s += g_ph[((size_t)(b * PP + p)) * FILT + c];
    int d = wpl[b * WW + w]; if (d < 1) d = 1;
    g_wd[((size_t)(b * WW + w)) * FILT + c] = s / (float)d;
}
__global__ void __launch_bounds__(256) mlp_kernel(
    const float* __restrict__ w1, const float* __restrict__ b1,
    const float* __restrict__ w2, const float* __restrict__ b2)
{
    __shared__ float sh[32 * FILT];
    int b = blockIdx.y, w0 = blockIdx.x * 32, o = threadIdx.x;
    for (int idx = o; idx < 32 * FILT; idx += 256)
        sh[idx] = g_wd[((size_t)(b * WW + w0)) * FILT + idx];
    __syncthreads();
    float acc[32];
    float bv = b1[o];
#pragma unroll
    for (int m = 0; m < 32; m++) acc[m] = bv;
    for (int i = 0; i < FILT; i++) {
        float wv = w1[i * FILT + o];
#pragma unroll
        for (int m = 0; m < 32; m++) acc[m] += sh[m * FILT + i] * wv;
    }
    __syncthreads();
#pragma unroll
    for (int m = 0; m < 32; m++) sh[m * FILT + o] = fmaxf(acc[m], 0.f);
    __syncthreads();
    int oo = o & (PDIM - 1);
    int mg = o >> 6;
    for (int m = mg * 8; m < mg * 8 + 8; m++) {
        float a = b2[oo];
        for (int i = 0; i < FILT; i++) a += sh[m * FILT + i] * w2[i * PDIM + oo];
        g_z[((size_t)(b * WW + w0 + m)) * PDIM + oo] = fmaxf(a, 0.f);
    }
}
__global__ void expand_kernel(const unsigned char* __restrict__ mask, float* __restrict__ out) {
    int b = blockIdx.y, p = blockIdx.x, o = threadIdx.x;
    const int* wc = g_wcum + b * WW;
    int lo = 0, hi = WW;
    while (lo < hi) { int mid = (lo + hi) >> 1; if (wc[mid] <= p) lo = mid + 1; else hi = mid; }
    int wid = lo; if (wid > WW - 1) wid = WW - 1;
    float v = g_z[((size_t)(b * WW + wid)) * PDIM + o];
    if (mask[b * PP + p]) v = 0.f;
    out[((size_t)(b * PP + p)) * PDIM + o] = v;
}

// ---------------- host launch -------------------------------------------------------
extern "C" void kernel_launch(void* const* d_in, const int* in_sizes, int n_in,
                              void* d_out, int out_size)
{
    const unsigned char* mask = (const unsigned char*)d_in[0];
    const float* mels = (const float*)d_in[1];
    const int* durations = (const int*)d_in[3];
    const int* wpl = (const int*)d_in[4];
    const float* c1w = (const float*)d_in[5];
    const float* c1b = (const float*)d_in[6];
    const float* l1g = (const float*)d_in[7];
    const float* l1b = (const float*)d_in[8];
    const float* c2w = (const float*)d_in[9];
    const float* c2b = (const float*)d_in[10];
    const float* l2g = (const float*)d_in[11];
    const float* l2b = (const float*)d_in[12];
    const float* w1 = (const float*)d_in[13];
    const float* b1 = (const float*)d_in[14];
    const float* w2 = (const float*)d_in[15];
    const float* b2 = (const float*)d_in[16];
    float* out = (float*)d_out;

    void *p_melhi, *p_melmid, *p_x1hi, *p_x1mid, *p_craw, *p_x2;
    void *p_w1h, *p_w1m, *p_w2h, *p_w2m;
    cudaGetSymbolAddress(&p_melhi, g_melhi);
    cudaGetSymbolAddress(&p_melmid, g_melmid);
    cudaGetSymbolAddress(&p_x1hi, g_x1hi);
    cudaGetSymbolAddress(&p_x1mid, g_x1mid);
    cudaGetSymbolAddress(&p_craw, g_craw);
    cudaGetSymbolAddress(&p_x2, g_x2);
    cudaGetSymbolAddress(&p_w1h, g_w1h);
    cudaGetSymbolAddress(&p_w1m, g_w1m);
    cudaGetSymbolAddress(&p_w2h, g_w2h);
    cudaGetSymbolAddress(&p_w2m, g_w2m);

    cudaFuncSetAttribute(conv_mma<3>, cudaFuncAttributeMaxDynamicSharedMemorySize, CONV_SMEM);
    cudaFuncSetAttribute(conv_mma<8>, cudaFuncAttributeMaxDynamicSharedMemorySize, CONV_SMEM);

    mel_split_kernel<<<(int)(((size_t)BB * TT * 96 + 255) / 256), 256>>>(mels);
    wsplit_kernel<NMEL, 96><<<(KK * FILT * 96 + 255) / 256, 256>>>(
        c1w, (__nv_bfloat16*)p_w1h, (__nv_bfloat16*)p_w1m);
    wsplit_kernel<FILT, FILT><<<(KK * FILT * FILT + 255) / 256, 256>>>(
        c2w, (__nv_bfloat16*)p_w2h, (__nv_bfloat16*)p_w2m);
    scan_kernel<<<BB, 32>>>(durations, wpl);

    dim3 cgrid(TT / 128, 2, BB);
    conv_mma<3><<<cgrid, 256, CONV_SMEM>>>(
        (const __nv_bfloat16*)p_melhi, (const __nv_bfloat16*)p_melmid,
        (const __nv_bfloat16*)p_w1h, (const __nv_bfloat16*)p_w1m, (float*)p_craw);
    ln_kernel<0><<<BB * TT / 8, 256>>>((const float*)p_craw, c1b, l1g, l1b,
        nullptr, (__nv_bfloat16*)p_x1hi, (__nv_bfloat16*)p_x1mid);
    conv_mma<8><<<cgrid, 256, CONV_SMEM>>>(
        (const __nv_bfloat16*)p_x1hi, (const __nv_bfloat16*)p_x1mid,
        (const __nv_bfloat16*)p_w2h, (const __nv_bfloat16*)p_w2m, (float*)p_craw);
    ln_kernel<1><<<BB * TT / 8, 256>>>((const float*)p_craw, c2b, l2g, l2b,
        (float*)p_x2, nullptr, nullptr);

    phone_pool_kernel<<<dim3(PP, BB), FILT>>>(durations);
    word_pool_kernel<<<dim3(WW, BB), FILT>>>(wpl);
    mlp_kernel<<<dim3(WW / 32, BB), 256>>>(w1, b1, w2, b2);
    expand_kernel<<<dim3(PP, BB), PDIM>>>(mask, out);
}